// round 15
// baseline (speedup 1.0000x reference)
#include <cuda_runtime.h>
#include <cuda_bf16.h>

// ---------------------------------------------------------------------------
// GraphEncoder relative-position attention, GB300 sm_103a — round 15
// R14 pipeline (2 syncs/tile) + RESTORED V-lo plane in PV (3-term MMA,
// rel_err back to ~1.7e-5; R14's 9.9e-4 was one reseed from failing).
// Split-softmax stat vectors relocated into the dead RELC region so
// Q/K/V hi+lo planes + RELC + W fit the exact 115448 B 2-CTA budget.
// ---------------------------------------------------------------------------

namespace {
constexpr int Bn  = 2;
constexpr int Sn  = 2048;
constexpr int Hn  = 768;
constexpr int NHn = 12;
constexpr int TILE_U32 = 2048;        // one 64x64 bf16 plane tile = 8192 B

// smem byte offsets (attention)
constexpr int QHo   = 0;         // Q hi plane (8192)
constexpr int QLo   = 8192;      // Q lo plane
constexpr int KHo   = 16384;     // K hi plane
constexpr int KLo   = 24576;     // K lo plane
constexpr int VHo   = 32768;     // V hi plane
constexpr int VLo   = 40960;     // V lo plane
constexpr int RELCo = 49152;     // relc bf16 [64][256] (32768)
constexpr int Wo    = 81920;     // W bf16 [254][66]    (33528)
constexpr int SMEMB = 115448;
// split-softmax stats: overlaid on RELC (dead after mainloop)
constexpr int MUAo  = RELCo;
constexpr int MUBo  = RELCo + 256;
constexpr int LAo   = RELCo + 512;
constexpr int LBo   = RELCo + 768;
constexpr int PLAo  = RELCo + 1024;
constexpr int PLBo  = RELCo + 1280;
constexpr int PHAo  = RELCo + 1536;
constexpr int PHBo  = RELCo + 1792;
// epilogue overlays (Q/K planes dead)
constexpr int CTXo  = 0;
constexpr int LVo   = 16384;
constexpr int PLOo  = 16640;
constexpr int PHIo  = 16896;
constexpr int MUo   = 17152;
}

typedef unsigned long long u64;
typedef unsigned int u32;

// pre-split bf16 plane tiles: [Bn*NHn*32 tiles][2048 u32]
__device__ u32 g_Qh[Bn * NHn * 32 * TILE_U32];
__device__ u32 g_Ql[Bn * NHn * 32 * TILE_U32];
__device__ u32 g_Kh[Bn * NHn * 32 * TILE_U32];
__device__ u32 g_Kl[Bn * NHn * 32 * TILE_U32];
__device__ u32 g_Vh[Bn * NHn * 32 * TILE_U32];
__device__ u32 g_Vl[Bn * NHn * 32 * TILE_U32];

__device__ __forceinline__ u64 pk2(float lo, float hi) {
    u64 r; asm("mov.b64 %0,{%1,%2};" : "=l"(r) : "f"(lo), "f"(hi)); return r;
}
__device__ __forceinline__ u64 dup2(float v) { return pk2(v, v); }
__device__ __forceinline__ u64 ffma2(u64 a, u64 b, u64 c) {
    u64 d; asm("fma.rn.f32x2 %0,%1,%2,%3;" : "=l"(d) : "l"(a), "l"(b), "l"(c)); return d;
}
__device__ __forceinline__ float2 up2(u64 v) {
    float2 f; asm("mov.b64 {%0,%1},%2;" : "=f"(f.x), "=f"(f.y) : "l"(v)); return f;
}
__device__ __forceinline__ u32 pkbf(float lo, float hi) {
    u32 d; asm("cvt.rn.bf16x2.f32 %0,%1,%2;" : "=r"(d) : "f"(hi), "f"(lo)); return d;
}
__device__ __forceinline__ float bflo(u32 h) { return __uint_as_float(h << 16); }
__device__ __forceinline__ float bfhi(u32 h) { return __uint_as_float(h & 0xFFFF0000u); }

// plane byte offset: 128B rows, 16B chunk ch swizzled by row bits
__device__ __forceinline__ int swq(int row, int ch) {
    return row * 128 + ((ch ^ (row & 7) ^ ((row >> 3) & 3)) << 4);
}

__device__ __forceinline__ void ldm_x4(u32& r0, u32& r1, u32& r2, u32& r3, u32 a) {
    asm volatile("ldmatrix.sync.aligned.m8n8.x4.shared.b16 {%0,%1,%2,%3},[%4];"
                 : "=r"(r0), "=r"(r1), "=r"(r2), "=r"(r3) : "r"(a));
}
__device__ __forceinline__ void ldm_x2(u32& r0, u32& r1, u32 a) {
    asm volatile("ldmatrix.sync.aligned.m8n8.x2.shared.b16 {%0,%1},[%2];"
                 : "=r"(r0), "=r"(r1) : "r"(a));
}
__device__ __forceinline__ void ldm_x4t(u32& r0, u32& r1, u32& r2, u32& r3, u32 a) {
    asm volatile("ldmatrix.sync.aligned.m8n8.x4.trans.shared.b16 {%0,%1,%2,%3},[%4];"
                 : "=r"(r0), "=r"(r1), "=r"(r2), "=r"(r3) : "r"(a));
}
__device__ __forceinline__ void mma_bf16(float* d, const u32* a, u32 b0, u32 b1) {
    asm volatile("mma.sync.aligned.m16n8k16.row.col.f32.bf16.bf16.f32 "
                 "{%0,%1,%2,%3},{%4,%5,%6,%7},{%8,%9},{%0,%1,%2,%3};"
                 : "+f"(d[0]), "+f"(d[1]), "+f"(d[2]), "+f"(d[3])
                 : "r"(a[0]), "r"(a[1]), "r"(a[2]), "r"(a[3]), "r"(b0), "r"(b1));
}

// ---- bf16 plane-tile copies ----
__device__ __forceinline__ void ldg_planes(const u32* __restrict__ gh,
                                           const u32* __restrict__ gl,
                                           float4 v[4], int tid)
{
    v[0] = __ldg((const float4*)gh + tid);
    v[1] = __ldg((const float4*)gh + tid + 256);
    v[2] = __ldg((const float4*)gl + tid);
    v[3] = __ldg((const float4*)gl + tid + 256);
}
__device__ __forceinline__ void sts_planes(const float4 v[4], char* smc,
                                           int hiOff, int loOff, int tid)
{
    *((float4*)(smc + hiOff) + tid)       = v[0];
    *((float4*)(smc + hiOff) + tid + 256) = v[1];
    *((float4*)(smc + loOff) + tid)       = v[2];
    *((float4*)(smc + loOff) + tid + 256) = v[3];
}

// ---- f32 tile -> split planes (rke / qkv X) ----
__device__ __forceinline__ void ldg_tile_s(const float* __restrict__ src,
                                           int stride, float4 v[4], int tid)
{
    #pragma unroll
    for (int s = 0; s < 4; s++) {
        int f = tid + s * 256;
        v[s] = __ldg((const float4*)(src + (size_t)(f >> 4) * stride + (f & 15) * 4));
    }
}
__device__ __forceinline__ void sts_split(const float4 v[4], char* smc,
                                          int hiOff, int loOff, int tid)
{
    #pragma unroll
    for (int s = 0; s < 4; s++) {
        int f = tid + s * 256;
        int row = f >> 4, cg = f & 15;
        float4 w = v[s];
        __nv_bfloat162 h0 = __floats2bfloat162_rn(w.x, w.y);
        __nv_bfloat162 h1 = __floats2bfloat162_rn(w.z, w.w);
        float2 f0 = __bfloat1622float2(h0);
        float2 f1 = __bfloat1622float2(h1);
        __nv_bfloat162 l0 = __floats2bfloat162_rn(w.x - f0.x, w.y - f0.y);
        __nv_bfloat162 l1 = __floats2bfloat162_rn(w.z - f1.x, w.w - f1.y);
        int off = swq(row, cg >> 1) + ((cg & 1) << 3);
        *(__nv_bfloat162*)(smc + hiOff + off)     = h0;
        *(__nv_bfloat162*)(smc + hiOff + off + 4) = h1;
        *(__nv_bfloat162*)(smc + loOff + off)     = l0;
        *(__nv_bfloat162*)(smc + loOff + off + 4) = l1;
    }
}
__device__ __forceinline__ void load_split_s(const float* __restrict__ src,
                                             int stride, char* smc,
                                             int hiOff, int loOff, int tid)
{
    float4 v[4];
    ldg_tile_s(src, stride, v, tid);
    sts_split(v, smc, hiOff, loOff, tid);
}

// 64x64x64 split-bf16 GEMM step: c[nt][e] += A(Q planes) . B(K planes)
__device__ __forceinline__ void mma_scores(float c[4][4], u32 smb,
                                           int wm, int wn, int lane)
{
    const int r8 = lane & 7;
    const int j4 = lane >> 3;
    const int jb = (lane >> 3) & 1;
    #pragma unroll
    for (int ks = 0; ks < 4; ks++) {
        int mrow = 16 * wm + r8 + (j4 & 1) * 8;
        int chA = 2 * ks + (j4 >> 1);
        u32 aAddr = smb + (u32)(QHo + swq(mrow, chA));
        u32 ah[4], al[4];
        ldm_x4(ah[0], ah[1], ah[2], ah[3], aAddr);
        ldm_x4(al[0], al[1], al[2], al[3], aAddr + (QLo - QHo));
        #pragma unroll
        for (int nt = 0; nt < 4; nt++) {
            int n = 32 * wn + 8 * nt + r8;
            int chB = 2 * ks + jb;
            u32 bAddr = smb + (u32)(KHo + swq(n, chB));
            u32 bh0, bh1, bl0, bl1;
            ldm_x2(bh0, bh1, bAddr);
            ldm_x2(bl0, bl1, bAddr + (KLo - KHo));
            mma_bf16(c[nt], ah, bh0, bh1);
            mma_bf16(c[nt], ah, bl0, bl1);
            mma_bf16(c[nt], al, bh0, bh1);
        }
    }
}

// ---------------------------------------------------------------------------
// Kernel 1: HMMA QKV projection -> pre-split bf16 plane tiles in gmem.
// ---------------------------------------------------------------------------
__global__ __launch_bounds__(256) void qkv_kernel(
    const float* __restrict__ X,
    const float* __restrict__ Wq, const float* __restrict__ bq,
    const float* __restrict__ Wk, const float* __restrict__ bk,
    const float* __restrict__ Wv, const float* __restrict__ bv)
{
    __shared__ char smc[32768];
    const u32 smb = (u32)__cvta_generic_to_shared(smc);

    const int z = blockIdx.z;
    const float* Wp = (z == 0) ? Wq : ((z == 1) ? Wk : Wv);
    const float* bp = (z == 0) ? bq : ((z == 1) ? bk : bv);
    u32* gh = (z == 0) ? g_Qh : ((z == 1) ? g_Kh : g_Vh);
    u32* gl = (z == 0) ? g_Ql : ((z == 1) ? g_Kl : g_Vl);
    const float sc = (z == 0) ? 0.125f : 1.0f;

    const int r0 = blockIdx.x * 64;
    const int hq = blockIdx.y;
    const int n0 = hq * 64;
    const int tid = threadIdx.x;
    const int lane = tid & 31;
    const int w = tid >> 5, wm = w & 3, wn = w >> 2;
    const int rb4 = lane & 3, rd4 = lane >> 2;

    float c[4][4] = {};
    float4 xr[4], wra[2], wrb[2];

    const int f0i = tid, f1i = tid + 256;
    const int kp0 = f0i >> 4, ng0 = f0i & 15;
    const int kp1 = f1i >> 4, ng1 = f1i & 15;

    ldg_tile_s(X + (size_t)r0 * 768, 768, xr, tid);
    {
        const float* w0 = Wp + (size_t)(2 * kp0) * 768 + n0 + ng0 * 4;
        const float* w1 = Wp + (size_t)(2 * kp1) * 768 + n0 + ng1 * 4;
        wra[0] = __ldg((const float4*)w0); wrb[0] = __ldg((const float4*)(w0 + 768));
        wra[1] = __ldg((const float4*)w1); wrb[1] = __ldg((const float4*)(w1 + 768));
    }

    for (int kt = 0; kt < 12; kt++) {
        __syncthreads();
        sts_split(xr, smc, QHo, QLo, tid);
        #pragma unroll
        for (int it = 0; it < 2; it++) {
            int kp = it ? kp1 : kp0, ng = it ? ng1 : ng0;
            int k0 = 2 * kp, nn = ng * 4;
            float av[4] = {it ? wra[1].x : wra[0].x, it ? wra[1].y : wra[0].y,
                           it ? wra[1].z : wra[0].z, it ? wra[1].w : wra[0].w};
            float bw[4] = {it ? wrb[1].x : wrb[0].x, it ? wrb[1].y : wrb[0].y,
                           it ? wrb[1].z : wrb[0].z, it ? wrb[1].w : wrb[0].w};
            #pragma unroll
            for (int i = 0; i < 4; i++) {
                int ni = nn + i;
                u32 hp = pkbf(av[i], bw[i]);
                u32 lp = pkbf(av[i] - bflo(hp), bw[i] - bfhi(hp));
                int off = swq(ni, k0 >> 3) + (k0 & 7) * 2;
                *(u32*)(smc + KHo + off) = hp;
                *(u32*)(smc + KLo + off) = lp;
            }
        }
        __syncthreads();
        if (kt < 11) {
            ldg_tile_s(X + (size_t)r0 * 768 + (kt + 1) * 64, 768, xr, tid);
            const float* w0 = Wp + (size_t)((kt + 1) * 64 + 2 * kp0) * 768 + n0 + ng0 * 4;
            const float* w1 = Wp + (size_t)((kt + 1) * 64 + 2 * kp1) * 768 + n0 + ng1 * 4;
            wra[0] = __ldg((const float4*)w0); wrb[0] = __ldg((const float4*)(w0 + 768));
            wra[1] = __ldg((const float4*)w1); wrb[1] = __ldg((const float4*)(w1 + 768));
        }
        mma_scores(c, smb, wm, wn, lane);
    }

    // epilogue: bias+scale, split to bf16 hi/lo plane tiles
    const int b  = r0 >> 11;
    const int jt = (r0 & 2047) >> 6;
    const size_t tilebase = ((size_t)(b * NHn + hq) * 32 + jt) * TILE_U32;
    #pragma unroll
    for (int nt = 0; nt < 4; nt++) {
        int d = 32 * wn + 8 * nt + 2 * rb4;
        float b0 = bp[n0 + d], b1 = bp[n0 + d + 1];
        #pragma unroll
        for (int half = 0; half < 2; half++) {
            int row = 16 * wm + rd4 + 8 * half;
            float v0 = (c[nt][2 * half + 0] + b0) * sc;
            float v1 = (c[nt][2 * half + 1] + b1) * sc;
            u32 hp = pkbf(v0, v1);
            u32 lp = pkbf(v0 - bflo(hp), v1 - bfhi(hp));
            int offu = (swq(row, d >> 3) + (d & 7) * 2) >> 2;
            gh[tilebase + offu] = hp;
            gl[tilebase + offu] = lp;
        }
    }
}

// ---------------------------------------------------------------------------
// Kernel 2: HMMA flash attention, 2-sync pipelined tile loop, 3-term PV.
// ---------------------------------------------------------------------------
__global__ __launch_bounds__(256, 2) void attn_kernel(
    const float* __restrict__ mask,
    const float* __restrict__ rke,
    const float* __restrict__ rve,
    float* __restrict__ out)
{
    extern __shared__ char smc[];
    __nv_bfloat16* smh = (__nv_bfloat16*)smc;
    const u32 smb = (u32)__cvta_generic_to_shared(smc);

    const int tid = threadIdx.x;
    const int lane = tid & 31;
    const int w = tid >> 5, wm = w & 3, wn = w >> 2;
    const int hq = blockIdx.y, bz = blockIdx.z;
    const int bh = bz * NHn + hq;
    const int i0 = blockIdx.x * 64;

    const size_t tb = (size_t)bh * 32;
    const float* maskg = mask + (size_t)bz * Sn;

    // ---- W init to -1e30 ----
    {
        __nv_bfloat16 hneg = __float2bfloat16(-1e30f);
        unsigned short us = __bfloat16_as_ushort(hneg);
        u32 vv = (u32)us | ((u32)us << 16);
        u32* w32 = (u32*)(smc + Wo);
        #pragma unroll
        for (int t = 0; t < 32; t++) w32[tid + t * 256] = vv;
        if (tid < 8382 - 32 * 256) w32[tid + 32 * 256] = vv;
    }

    // ---- Q planes: pure copy ----
    {
        float4 qv[4];
        ldg_planes(g_Qh + (tb + blockIdx.x) * TILE_U32,
                   g_Ql + (tb + blockIdx.x) * TILE_U32, qv, tid);
        sts_planes(qv, smc, QHo, QLo, tid);
    }
    __syncthreads();

    const int rb4 = lane & 3, rd4 = lane >> 2;
    // ---- relc via MMA (rke f32 -> split into K planes) ----
    for (int rb = 0; rb < 4; rb++) {
        load_split_s(rke + rb * 64 * 64, 64, smc, KHo, KLo, tid);
        __syncthreads();
        float c[4][4] = {};
        mma_scores(c, smb, wm, wn, lane);
        #pragma unroll
        for (int nt = 0; nt < 4; nt++) {
            #pragma unroll
            for (int e = 0; e < 4; e++) {
                int m = 16 * wm + rd4 + (e >> 1) * 8;
                int r = rb * 64 + 32 * wn + 8 * nt + 2 * rb4 + (e & 1);
                smh[(RELCo >> 1) + m * 256 + r] = __float2bfloat16(c[nt][e]);
            }
        }
        __syncthreads();
    }

    float ctx[8][4] = {};
    float mu[2] = {-1e30f, -1e30f}, l[2] = {}, plo[2] = {}, phi[2] = {};
    const int rbase = 16 * wm + rd4;

    // ---- pipeline prologue: stage K0, prefetch V0 and K1 ----
    float4 kr[4], vr[4];
    ldg_planes(g_Kh + tb * TILE_U32, g_Kl + tb * TILE_U32, kr, tid);
    sts_planes(kr, smc, KHo, KLo, tid);
    ldg_planes(g_Vh + tb * TILE_U32, g_Vl + tb * TILE_U32, vr, tid);
    ldg_planes(g_Kh + (tb + 1) * TILE_U32, g_Kl + (tb + 1) * TILE_U32, kr, tid);
    __syncthreads();   // K0 ready

    for (int jt = 0; jt < 32; jt++) {
        const int j0 = jt * 64;
        const int doff = j0 - i0;

        float c[4][4] = {};
        mma_scores(c, smb, wm, wn, lane);   // K_jt

        float mb[4][2];
        #pragma unroll
        for (int nt = 0; nt < 4; nt++) {
            float2 mv = __ldg((const float2*)(maskg + j0 + 32 * wn + 8 * nt + 2 * rb4));
            mb[nt][0] = (1.0f - mv.x) * -10000.0f;
            mb[nt][1] = (1.0f - mv.y) * -10000.0f;
        }

        const bool pure_lo = (doff + 63 <= -128);
        const bool pure_hi = (doff - 63 >= 127);
        const bool pure = pure_lo || pure_hi;
        const bool has_clamp = !pure && !((doff - 63 >= -127) && (doff + 63 <= 126));

        if (pure) {
            const int b = pure_lo ? 0 : 255;
            float rb0 = __bfloat162float(smh[(RELCo >> 1) + rbase * 256 + b]);
            float rb1 = __bfloat162float(smh[(RELCo >> 1) + (rbase + 8) * 256 + b]);
            #pragma unroll
            for (int nt = 0; nt < 4; nt++)
                #pragma unroll
                for (int e = 0; e < 4; e++)
                    c[nt][e] += ((e >> 1) ? rb1 : rb0) + mb[nt][e & 1];
        } else {
            #pragma unroll
            for (int nt = 0; nt < 4; nt++) {
                #pragma unroll
                for (int e = 0; e < 4; e++) {
                    int row = rbase + (e >> 1) * 8;
                    int col = 32 * wn + 8 * nt + 2 * rb4 + (e & 1);
                    int dlt = doff + col - row;
                    int bkt = max(-128, min(127, dlt)) + 128;
                    c[nt][e] += __bfloat162float(
                                    smh[(RELCo >> 1) + row * 256 + bkt]) + mb[nt][e & 1];
                    if (dlt > -128 && dlt < 127)
                        smh[(Wo >> 1) + (dlt + 127) * 66 + row] = __float2bfloat16(c[nt][e]);
                }
            }
        }

        // ---- per-half online softmax (warp-local) ----
        float alpha[2];
        #pragma unroll
        for (int rl = 0; rl < 2; rl++) {
            int row = rbase + 8 * rl;
            float rm = fmaxf(fmaxf(c[0][2 * rl], c[0][2 * rl + 1]),
                             fmaxf(c[1][2 * rl], c[1][2 * rl + 1]));
            rm = fmaxf(rm, fmaxf(fmaxf(c[2][2 * rl], c[2][2 * rl + 1]),
                                 fmaxf(c[3][2 * rl], c[3][2 * rl + 1])));
            rm = fmaxf(rm, __shfl_xor_sync(0xffffffffu, rm, 1));
            rm = fmaxf(rm, __shfl_xor_sync(0xffffffffu, rm, 2));
            float nm = fmaxf(mu[rl], rm);
            alpha[rl] = __expf(mu[rl] - nm);
            mu[rl] = nm;
            float sum = 0.f;
            #pragma unroll
            for (int nt = 0; nt < 4; nt++) {
                #pragma unroll
                for (int h = 0; h < 2; h++) {
                    int e = 2 * rl + h;
                    float p = __expf(c[nt][e] - nm);
                    c[nt][e] = p;
                    sum += p;
                }
            }
            sum += __shfl_xor_sync(0xffffffffu, sum, 1);
            sum += __shfl_xor_sync(0xffffffffu, sum, 2);
            l[rl] = l[rl] * alpha[rl] + sum;
            float addlo = 0.f, addhi = 0.f;
            if (pure_lo)      addlo = sum;
            else if (pure_hi) addhi = sum;
            else if (has_clamp) {
                float clo = 0.f, chi = 0.f;
                #pragma unroll
                for (int nt = 0; nt < 4; nt++) {
                    #pragma unroll
                    for (int h = 0; h < 2; h++) {
                        int col = 32 * wn + 8 * nt + 2 * rb4 + h;
                        int dlt = doff + col - row;
                        float p = c[nt][2 * rl + h];
                        if (dlt <= -128)     clo += p;
                        else if (dlt >= 127) chi += p;
                    }
                }
                clo += __shfl_xor_sync(0xffffffffu, clo, 1);
                clo += __shfl_xor_sync(0xffffffffu, clo, 2);
                chi += __shfl_xor_sync(0xffffffffu, chi, 1);
                chi += __shfl_xor_sync(0xffffffffu, chi, 2);
                addlo = clo; addhi = chi;
            }
            plo[rl] = plo[rl] * alpha[rl] + addlo;
            phi[rl] = phi[rl] * alpha[rl] + addhi;
        }
        #pragma unroll
        for (int dnt = 0; dnt < 8; dnt++) {
            ctx[dnt][0] *= alpha[0]; ctx[dnt][1] *= alpha[0];
            ctx[dnt][2] *= alpha[1]; ctx[dnt][3] *= alpha[1];
        }

        // pack P fragments (hi/lo)
        u32 Ah[2][4], Al[2][4];
        #pragma unroll
        for (int kf = 0; kf < 2; kf++) {
            #pragma unroll
            for (int h = 0; h < 2; h++) {
                int nt = 2 * kf + h;
                u32 h0 = pkbf(c[nt][0], c[nt][1]);
                u32 h1 = pkbf(c[nt][2], c[nt][3]);
                Ah[kf][2 * h]     = h0;
                Ah[kf][2 * h + 1] = h1;
                Al[kf][2 * h]     = pkbf(c[nt][0] - bflo(h0), c[nt][1] - bfhi(h0));
                Al[kf][2 * h + 1] = pkbf(c[nt][2] - bflo(h1), c[nt][3] - bfhi(h1));
            }
        }

        __syncthreads();   // prev PV V-reads + this tile's K-reads done
        sts_planes(vr, smc, VHo, VLo, tid);               // V_jt
        if (jt < 31) sts_planes(kr, smc, KHo, KLo, tid);  // K_{jt+1}
        if (jt < 31)
            ldg_planes(g_Vh + (tb + jt + 1) * TILE_U32,
                       g_Vl + (tb + jt + 1) * TILE_U32, vr, tid);
        if (jt < 30)
            ldg_planes(g_Kh + (tb + jt + 2) * TILE_U32,
                       g_Kl + (tb + jt + 2) * TILE_U32, kr, tid);
        __syncthreads();   // V_jt + K_{jt+1} ready

        // ---- PV (3-term): ctx += Ph.Vh + Ph.Vl + Pl.Vh ----
        {
            int vrow = 32 * wn + lane;
            #pragma unroll
            for (int dnt = 0; dnt < 8; dnt++) {
                u32 vAddr = smb + (u32)(VHo + swq(vrow, dnt));
                u32 bhv[4], blv[4];
                ldm_x4t(bhv[0], bhv[1], bhv[2], bhv[3], vAddr);
                ldm_x4t(blv[0], blv[1], blv[2], blv[3], vAddr + (VLo - VHo));
                #pragma unroll
                for (int kf = 0; kf < 2; kf++) {
                    mma_bf16(ctx[dnt], Ah[kf], bhv[2 * kf], bhv[2 * kf + 1]);
                    mma_bf16(ctx[dnt], Ah[kf], blv[2 * kf], blv[2 * kf + 1]);
                    mma_bf16(ctx[dnt], Al[kf], bhv[2 * kf], bhv[2 * kf + 1]);
                }
            }
        }
    }

    // ---- epilogue: per-half stats (in dead RELC region), merge, combine ----
    float* muA = (float*)(smc + MUAo);
    float* muB = (float*)(smc + MUBo);
    float* lA  = (float*)(smc + LAo);
    float* lB  = (float*)(smc + LBo);
    float* plA = (float*)(smc + PLAo);
    float* plB = (float*)(smc + PLBo);
    float* phA = (float*)(smc + PHAo);
    float* phB = (float*)(smc + PHBo);
    __syncthreads();
    if ((lane & 3) == 0) {
        #pragma unroll
        for (int rl = 0; rl < 2; rl++) {
            int row = rbase + 8 * rl;
            if (wn == 0) { muA[row] = mu[rl]; lA[row] = l[rl];
                           plA[row] = plo[rl]; phA[row] = phi[rl]; }
            else         { muB[row] = mu[rl]; lB[row] = l[rl];
                           plB[row] = plo[rl]; phB[row] = phi[rl]; }
        }
    }
    __syncthreads();

    float* ctxp = (float*)(smc + CTXo);
    float* lv   = (float*)(smc + LVo);
    float* plv  = (float*)(smc + PLOo);
    float* phv  = (float*)(smc + PHIo);
    float* muv  = (float*)(smc + MUo);
    float fw[2];
    #pragma unroll
    for (int rl = 0; rl < 2; rl++) {
        int row = rbase + 8 * rl;
        float M = fmaxf(muA[row], muB[row]);
        fw[rl] = __expf((wn == 0 ? muA[row] : muB[row]) - M);
        if (wn == 0 && (lane & 3) == 0) {
            float fa = __expf(muA[row] - M), fb = __expf(muB[row] - M);
            lv[row]  = lA[row]  * fa + lB[row]  * fb;
            plv[row] = plA[row] * fa + plB[row] * fb;
            phv[row] = phA[row] * fa + phB[row] * fb;
            muv[row] = M;
        }
    }
    if (wn == 0) {
        #pragma unroll
        for (int dnt = 0; dnt < 8; dnt++) {
            int dbase = 8 * dnt + 2 * rb4;
            *(float2*)&ctxp[rbase * 64 + dbase] =
                make_float2(ctx[dnt][0] * fw[0], ctx[dnt][1] * fw[0]);
            *(float2*)&ctxp[(rbase + 8) * 64 + dbase] =
                make_float2(ctx[dnt][2] * fw[1], ctx[dnt][3] * fw[1]);
        }
    }
    __syncthreads();
    if (wn == 1) {
        #pragma unroll
        for (int dnt = 0; dnt < 8; dnt++) {
            int dbase = 8 * dnt + 2 * rb4;
            float2 a0 = *(float2*)&ctxp[rbase * 64 + dbase];
            float2 a1 = *(float2*)&ctxp[(rbase + 8) * 64 + dbase];
            *(float2*)&ctxp[rbase * 64 + dbase] =
                make_float2(a0.x + ctx[dnt][0] * fw[0], a0.y + ctx[dnt][1] * fw[0]);
            *(float2*)&ctxp[(rbase + 8) * 64 + dbase] =
                make_float2(a1.x + ctx[dnt][2] * fw[1], a1.y + ctx[dnt][3] * fw[1]);
        }
    }
    __syncthreads();

    // ---- E-pass: W := exp(W - mu[m]) ----
    #pragma unroll 4
    for (int t = 0; t < 64; t++) {
        int idx = tid + t * 256;
        if (idx < 254 * 64) {
            int r = idx >> 6, m = idx & 63;
            float wv = __bfloat162float(smh[(Wo >> 1) + r * 66 + m]);
            smh[(Wo >> 1) + r * 66 + m] = __float2bfloat16(__expf(wv - muv[m]));
        }
    }
    __syncthreads();

    // ---- rve GEMM + final ----
    {
        const int ty = tid >> 5, tx = tid & 31;
        u64 o2[4][2];
        #pragma unroll
        for (int rp = 0; rp < 4; rp++)
            #pragma unroll
            for (int di = 0; di < 2; di++)
                o2[rp][di] = pk2(ctxp[(ty * 8 + 2 * rp) * 64 + tx * 2 + di],
                                 ctxp[(ty * 8 + 2 * rp + 1) * 64 + tx * 2 + di]);

        #pragma unroll 2
        for (int r = 0; r < 254; r++) {
            const __nv_bfloat162* wr =
                (const __nv_bfloat162*)&smh[(Wo >> 1) + r * 66 + ty * 8];
            __nv_bfloat162 e0 = wr[0], e1 = wr[1], e2 = wr[2], e3 = wr[3];
            float2 rv = __ldg((const float2*)(rve + (r + 1) * 64 + tx * 2));
            u64 r0 = dup2(rv.x), r1 = dup2(rv.y);
            float2 f0 = __bfloat1622float2(e0);
            float2 f1 = __bfloat1622float2(e1);
            float2 f2 = __bfloat1622float2(e2);
            float2 f3 = __bfloat1622float2(e3);
            u64 ep0 = pk2(f0.x, f0.y), ep1 = pk2(f1.x, f1.y);
            u64 ep2 = pk2(f2.x, f2.y), ep3 = pk2(f3.x, f3.y);
            o2[0][0] = ffma2(ep0, r0, o2[0][0]);
            o2[0][1] = ffma2(ep0, r1, o2[0][1]);
            o2[1][0] = ffma2(ep1, r0, o2[1][0]);
            o2[1][1] = ffma2(ep1, r1, o2[1][1]);
            o2[2][0] = ffma2(ep2, r0, o2[2][0]);
            o2[2][1] = ffma2(ep2, r1, o2[2][1]);
            o2[3][0] = ffma2(ep3, r0, o2[3][0]);
            o2[3][1] = ffma2(ep3, r1, o2[3][1]);
        }

        float2 rv0 = __ldg((const float2*)(rve + 0 * 64 + tx * 2));
        float2 rvN = __ldg((const float2*)(rve + 255 * 64 + tx * 2));
        #pragma unroll
        for (int rp = 0; rp < 4; rp++) {
            float2 c0 = up2(o2[rp][0]), c1 = up2(o2[rp][1]);
            #pragma unroll
            for (int h = 0; h < 2; h++) {
                int ri = 2 * rp + h;
                int row = ty * 8 + ri;
                float ox = h ? c0.y : c0.x;
                float oy = h ? c1.y : c1.x;
                float inv = 1.0f / lv[row];
                float2 res;
                res.x = (ox + plv[row] * rv0.x + phv[row] * rvN.x) * inv;
                res.y = (oy + plv[row] * rv0.y + phv[row] * rvN.y) * inv;
                *(float2*)(out + ((size_t)bz * Sn + i0 + row) * Hn + hq * 64 + tx * 2) = res;
            }
        }
    }
}

// ---------------------------------------------------------------------------
extern "C" void kernel_launch(void* const* d_in, const int* in_sizes, int n_in,
                              void* d_out, int out_size)
{
    const float* X    = (const float*)d_in[0];
    const float* mask = (const float*)d_in[1];
    const float* Wq   = (const float*)d_in[2];
    const float* bq   = (const float*)d_in[3];
    const float* Wk   = (const float*)d_in[4];
    const float* bk   = (const float*)d_in[5];
    const float* Wv   = (const float*)d_in[6];
    const float* bv   = (const float*)d_in[7];
    const float* rke  = (const float*)d_in[8];
    const float* rve  = (const float*)d_in[9];
    float* out = (float*)d_out;

    (void)in_sizes; (void)n_in; (void)out_size;

    cudaFuncSetAttribute(attn_kernel,
                         cudaFuncAttributeMaxDynamicSharedMemorySize, SMEMB);

    qkv_kernel<<<dim3(64, NHn, 3), 256>>>(X, Wq, bq, Wk, bk, Wv, bv);
    attn_kernel<<<dim3(32, NHn, Bn), 256, SMEMB>>>(mask, rke, rve, out);
}